// round 2
// baseline (speedup 1.0000x reference)
#include <cuda_runtime.h>
#include <math.h>

#define Bsz  64
#define Ssz  256
#define INP  400
#define Hsz  1024
#define H4   4096
#define Gsz  8192
#define NS   150
#define NR   50
#define NBLK 128

// ---------------- scratch (static device allocations are the sanctioned path) ----
static __device__ float    d_Xg[(size_t)Ssz * Gsz * Bsz];   // [s][col(8192)][b]  512MB
static __device__ float    d_Hbuf[2 * Bsz * Hsz];           // [cell][b][j]
static __device__ float    d_T[Bsz * Hsz];                  // recurrent hidden T
static __device__ unsigned g_bar;                           // zero-init
static __device__ unsigned g_gen;                           // zero-init, monotonic

// ---------------- grid barrier (all NBLK blocks resident by construction) -------
__device__ __forceinline__ void gridbar(unsigned& gen) {
    __syncthreads();
    if (threadIdx.x == 0) {
        __threadfence();                       // release producer data
        unsigned arrived = atomicAdd(&g_bar, 1u);
        if (arrived == NBLK - 1) {
            atomicExch(&g_bar, 0u);
            __threadfence();
            atomicAdd(&g_gen, 1u);
        } else {
            while (atomicAdd(&g_gen, 0u) == gen) { /* spin on L2 */ }
        }
        __threadfence();                       // acquire
    }
    __syncthreads();
    gen++;
}

// =================================================================================
// Phase A: Xg[s, col, b] = sum_k x[b,s,k] * Wih_cat[col,k] + (bih+bhh)[col]
// grid = (128 col-tiles, 256 s), 256 threads, 64x64 tile, 4x4 microtile, K chunks 16
// =================================================================================
__global__ void __launch_bounds__(256) phaseA_kernel(
    const float* __restrict__ x,
    const float* __restrict__ WihF, const float* __restrict__ WihR,
    const float* __restrict__ bihF, const float* __restrict__ bhhF,
    const float* __restrict__ bihR, const float* __restrict__ bhhR)
{
    const int s    = blockIdx.y;
    const int col0 = blockIdx.x << 6;
    const int tid  = threadIdx.x;
    const int tx = tid & 15, ty = tid >> 4;
    const int lb = tid >> 2, lk = (tid & 3) << 2;

    __shared__ float xs[16][68];   // [kk][b]
    __shared__ float ws[16][68];   // [kk][c]

    const int colL = col0 + lb;
    const float* wrow = (colL < H4) ? (WihF + (size_t)colL * INP)
                                    : (WihR + (size_t)(colL - H4) * INP);
    const float* xrow = x + ((size_t)lb * Ssz + s) * INP;

    float acc[4][4];
#pragma unroll
    for (int j = 0; j < 4; ++j)
#pragma unroll
        for (int i = 0; i < 4; ++i) acc[j][i] = 0.f;

    float4 tX = *reinterpret_cast<const float4*>(xrow + lk);
    float4 tW = *reinterpret_cast<const float4*>(wrow + lk);

    for (int k0 = 0; k0 < INP; k0 += 16) {
        xs[lk+0][lb] = tX.x; xs[lk+1][lb] = tX.y; xs[lk+2][lb] = tX.z; xs[lk+3][lb] = tX.w;
        ws[lk+0][lb] = tW.x; ws[lk+1][lb] = tW.y; ws[lk+2][lb] = tW.z; ws[lk+3][lb] = tW.w;
        __syncthreads();
        if (k0 + 16 < INP) {
            tX = *reinterpret_cast<const float4*>(xrow + k0 + 16 + lk);
            tW = *reinterpret_cast<const float4*>(wrow + k0 + 16 + lk);
        }
#pragma unroll
        for (int kk = 0; kk < 16; ++kk) {
            float4 bv = *reinterpret_cast<const float4*>(&xs[kk][ty << 2]);
            float4 wv = *reinterpret_cast<const float4*>(&ws[kk][tx << 2]);
            const float bb[4] = {bv.x, bv.y, bv.z, bv.w};
            const float ww[4] = {wv.x, wv.y, wv.z, wv.w};
#pragma unroll
            for (int j = 0; j < 4; ++j)
#pragma unroll
                for (int i = 0; i < 4; ++i) acc[j][i] = fmaf(ww[j], bb[i], acc[j][i]);
        }
        __syncthreads();
    }

#pragma unroll
    for (int j = 0; j < 4; ++j) {
        int col = col0 + (tx << 2) + j;
        float bias = (col < H4) ? (bihF[col] + bhhF[col])
                                : (bihR[col - H4] + bhhR[col - H4]);
        float4 v = make_float4(acc[j][0] + bias, acc[j][1] + bias,
                               acc[j][2] + bias, acc[j][3] + bias);
        *reinterpret_cast<float4*>(&d_Xg[((size_t)s * Gsz + col) * Bsz + (ty << 2)]) = v;
    }
}

// =================================================================================
// Phase B: persistent kernel, 128 blocks x 256 threads, 256 sequential steps.
// Block blk: cell = blk>>6, hidden units [j0, j0+16) (x4 gates = 64 g-columns).
// Step: g-tile GEMM (T @ Whh_slice^T + Xg) -> gates -> h ; barrier ;
//       blocks 0..63: attention + softmax + items + outer product -> T, outputs ;
//       barrier.
// =================================================================================
__global__ void __launch_bounds__(256) phaseB_kernel(
    const float* __restrict__ WhhF, const float* __restrict__ WhhR,
    const float* __restrict__ WaFw, const float* __restrict__ WaFb,
    const float* __restrict__ WaRw, const float* __restrict__ WaRb,
    const float* __restrict__ Fw,   const float* __restrict__ Fb,
    const float* __restrict__ Rw,   const float* __restrict__ Rb,
    float* __restrict__ out)
{
    const int tid  = threadIdx.x;
    const int blk  = blockIdx.x;
    const int cell = blk >> 6;
    const int j0   = (blk & 63) << 4;
    const float* Whh = cell ? WhhR : WhhF;

    __shared__ float Ts[16][68];     // [kk][b]
    __shared__ float Ws[16][68];     // [kk][c]
    __shared__ float gs[64][65];     // [b][c]   c = gate*16 + u
    __shared__ float hsh[2 * Hsz];   // hF | hR for one batch
    __shared__ float lg[256];        // logits / attention weights (200 used)
    __shared__ float items[64];      // itemF[32] | itemR[32]
    __shared__ unsigned s_gen;

    const int tx = tid & 15, ty = tid >> 4;
    const int lb = tid >> 2, lk = (tid & 3) << 2;

    // W row this thread streams (fixed across steps)
    const int   wgate = lb >> 4, wu = lb & 15;
    const float* wrow = Whh + (size_t)(wgate * Hsz + j0 + wu) * Hsz;

    // epilogue mapping: (unit eu, 4 batches eb4*4+i); cell state in registers
    const int eu  = tid & 15;
    const int eb4 = tid >> 4;
    float cst[4] = {0.f, 0.f, 0.f, 0.f};

    // init shared hidden T = 0 (L2-visible for __ldcg readers)
    if (blk < Bsz) {
        for (int j = tid; j < Hsz; j += 256) __stcg(&d_T[blk * Hsz + j], 0.f);
    }
    if (tid == 0) s_gen = atomicAdd(&g_gen, 0u);
    __syncthreads();
    unsigned gen = s_gen;
    gridbar(gen);

    float* outAF = out + (size_t)Bsz * Ssz * Hsz;
    float* outAR = outAF + (size_t)Bsz * Ssz * NS;

    for (int s = 0; s < Ssz; ++s) {
        // ---- prefetch this block's Xg slice (batches ty*4.., cols tx*4..) ----
        float4 xgv[4];
#pragma unroll
        for (int j = 0; j < 4; ++j) {
            int c = (tx << 2) + j;
            int gate = c >> 4, u = c & 15;
            size_t grow = (size_t)cell * H4 + (size_t)gate * Hsz + j0 + u;
            xgv[j] = *reinterpret_cast<const float4*>(
                &d_Xg[((size_t)s * Gsz + grow) * Bsz + (ty << 2)]);
        }

        // ---- GEMM: acc[c][b] = T[b,:] . Whh_row(c)  (K=1024, chunks of 16) ----
        float acc[4][4];
#pragma unroll
        for (int j = 0; j < 4; ++j)
#pragma unroll
            for (int i = 0; i < 4; ++i) acc[j][i] = 0.f;

        float4 tA = __ldcg(reinterpret_cast<const float4*>(&d_T[lb * Hsz + lk]));
        float4 tW = __ldg (reinterpret_cast<const float4*>(&wrow[lk]));
        for (int k0 = 0; k0 < Hsz; k0 += 16) {
            Ts[lk+0][lb] = tA.x; Ts[lk+1][lb] = tA.y; Ts[lk+2][lb] = tA.z; Ts[lk+3][lb] = tA.w;
            Ws[lk+0][lb] = tW.x; Ws[lk+1][lb] = tW.y; Ws[lk+2][lb] = tW.z; Ws[lk+3][lb] = tW.w;
            __syncthreads();
            if (k0 + 16 < Hsz) {
                tA = __ldcg(reinterpret_cast<const float4*>(&d_T[lb * Hsz + k0 + 16 + lk]));
                tW = __ldg (reinterpret_cast<const float4*>(&wrow[k0 + 16 + lk]));
            }
#pragma unroll
            for (int kk = 0; kk < 16; ++kk) {
                float4 bv = *reinterpret_cast<const float4*>(&Ts[kk][ty << 2]);
                float4 wv = *reinterpret_cast<const float4*>(&Ws[kk][tx << 2]);
                const float bb[4] = {bv.x, bv.y, bv.z, bv.w};
                const float ww[4] = {wv.x, wv.y, wv.z, wv.w};
#pragma unroll
                for (int j = 0; j < 4; ++j)
#pragma unroll
                    for (int i = 0; i < 4; ++i) acc[j][i] = fmaf(ww[j], bb[i], acc[j][i]);
            }
            __syncthreads();
        }

        // ---- g = acc + Xg  -> shared, then gates ----
#pragma unroll
        for (int j = 0; j < 4; ++j) {
            const float* xg = reinterpret_cast<const float*>(&xgv[j]);
#pragma unroll
            for (int i = 0; i < 4; ++i)
                gs[(ty << 2) + i][(tx << 2) + j] = acc[j][i] + xg[i];
        }
        __syncthreads();

#pragma unroll
        for (int i = 0; i < 4; ++i) {
            int b = (eb4 << 2) + i;
            float iv = gs[b][eu      ];
            float fv = gs[b][16 + eu ];
            float gv = gs[b][32 + eu ];
            float ov = gs[b][48 + eu ];
            float si = 1.f / (1.f + __expf(-iv));
            float sf = 1.f / (1.f + __expf(-fv));
            float so = 1.f / (1.f + __expf(-ov));
            float c2 = sf * cst[i] + si * tanhf(gv);
            cst[i] = c2;
            float h = so * tanhf(c2);
            __stcg(&d_Hbuf[((size_t)cell * Bsz + b) * Hsz + j0 + eu], h);
        }

        gridbar(gen);   // h complete

        // ---- attention + output: block b (< 64) handles batch b ----
        if (blk < Bsz) {
            const int b = blk;
            for (int i = tid; i < 2 * Hsz; i += 256) {
                int c2 = i >> 10;
                int k  = i & (Hsz - 1);
                hsh[i] = __ldcg(&d_Hbuf[((size_t)c2 * Bsz + b) * Hsz + k]);
            }
            __syncthreads();

            const int warp = tid >> 5, lane = tid & 31;
            for (int r = warp; r < NS + NR; r += 8) {
                const float* wr; const float* hh; float bias;
                if (r < NS) { wr = WaFw + (size_t)r * Hsz;        hh = hsh;       bias = WaFb[r]; }
                else        { wr = WaRw + (size_t)(r - NS) * Hsz; hh = hsh + Hsz; bias = WaRb[r - NS]; }
                float sum = 0.f;
                for (int k = lane; k < Hsz; k += 32) sum = fmaf(__ldg(&wr[k]), hh[k], sum);
#pragma unroll
                for (int off = 16; off; off >>= 1) sum += __shfl_down_sync(0xffffffffu, sum, off);
                if (lane == 0) lg[r] = sum + bias;
            }
            __syncthreads();

            // softmax: warp0 -> F(150), warp1 -> R(50); writes aF/aR outputs too
            if (warp == 0) {
                float m = -1e30f;
                for (int n = lane; n < NS; n += 32) m = fmaxf(m, lg[n]);
#pragma unroll
                for (int off = 16; off; off >>= 1) m = fmaxf(m, __shfl_xor_sync(0xffffffffu, m, off));
                float ssum = 0.f;
                for (int n = lane; n < NS; n += 32) { float e = __expf(lg[n] - m); lg[n] = e; ssum += e; }
#pragma unroll
                for (int off = 16; off; off >>= 1) ssum += __shfl_xor_sync(0xffffffffu, ssum, off);
                float inv = 1.f / ssum;
                for (int n = lane; n < NS; n += 32) {
                    float a = lg[n] * inv; lg[n] = a;
                    outAF[((size_t)b * Ssz + s) * NS + n] = a;
                }
            } else if (warp == 1) {
                float m = -1e30f;
                for (int n = lane; n < NR; n += 32) m = fmaxf(m, lg[NS + n]);
#pragma unroll
                for (int off = 16; off; off >>= 1) m = fmaxf(m, __shfl_xor_sync(0xffffffffu, m, off));
                float ssum = 0.f;
                for (int n = lane; n < NR; n += 32) { float e = __expf(lg[NS + n] - m); lg[NS + n] = e; ssum += e; }
#pragma unroll
                for (int off = 16; off; off >>= 1) ssum += __shfl_xor_sync(0xffffffffu, ssum, off);
                float inv = 1.f / ssum;
                for (int n = lane; n < NR; n += 32) {
                    float a = lg[NS + n] * inv; lg[NS + n] = a;
                    outAR[((size_t)b * Ssz + s) * NR + n] = a;
                }
            }
            __syncthreads();

            // items: itemF[d] = aF . Fw[d,:] + Fb[d] ; itemR likewise
            if (tid < 32) {
                float sum = Fb[tid];
                for (int n = 0; n < NS; ++n) sum = fmaf(lg[n], __ldg(&Fw[tid * NS + n]), sum);
                items[tid] = sum;
            } else if (tid < 64) {
                int d = tid - 32;
                float sum = Rb[d];
                for (int n = 0; n < NR; ++n) sum = fmaf(lg[NS + n], __ldg(&Rw[d * NR + n]), sum);
                items[32 + d] = sum;
            }
            __syncthreads();

            // T[b, ds*32+dr] = itemF[ds]*itemR[dr]; also the main output
            for (int j = tid; j < Hsz; j += 256) {
                float v = items[j >> 5] * items[32 + (j & 31)];
                __stcg(&d_T[b * Hsz + j], v);
                out[((size_t)b * Ssz + s) * Hsz + j] = v;
            }
        }

        gridbar(gen);   // T complete for next step
    }
}

// =================================================================================
extern "C" void kernel_launch(void* const* d_in, const int* in_sizes, int n_in,
                              void* d_out, int out_size) {
    (void)in_sizes; (void)n_in; (void)out_size;
    const float* x    = (const float*)d_in[0];
    const float* WihF = (const float*)d_in[1];
    const float* WhhF = (const float*)d_in[2];
    const float* bihF = (const float*)d_in[3];
    const float* bhhF = (const float*)d_in[4];
    const float* WihR = (const float*)d_in[5];
    const float* WhhR = (const float*)d_in[6];
    const float* bihR = (const float*)d_in[7];
    const float* bhhR = (const float*)d_in[8];
    const float* WaFw = (const float*)d_in[9];
    const float* WaFb = (const float*)d_in[10];
    const float* WaRw = (const float*)d_in[11];
    const float* WaRb = (const float*)d_in[12];
    const float* Fw   = (const float*)d_in[13];
    const float* Fb   = (const float*)d_in[14];
    const float* Rw   = (const float*)d_in[15];
    const float* Rb   = (const float*)d_in[16];
    float* out = (float*)d_out;

    phaseA_kernel<<<dim3(128, 256), 256>>>(x, WihF, WihR, bihF, bhhF, bihR, bhhR);
    phaseB_kernel<<<NBLK, 256>>>(WhhF, WhhR, WaFw, WaFb, WaRw, WaRb, Fw, Fb, Rw, Rb, out);
}

// round 4
// speedup vs baseline: 1.4517x; 1.4517x over previous
#include <cuda_runtime.h>
#include <cuda_bf16.h>
#include <cstdint>
#include <math.h>

#define Bsz  64
#define Ssz  256
#define INP  400
#define Hsz  1024
#define H4   4096
#define Gsz  8192
#define NS   150
#define NR   50
#define NBLK 128

// ------------------------------- device scratch ---------------------------------
static __device__ float    d_Xg[(size_t)Ssz * Gsz * Bsz];   // [s][col(8192)][b]
static __device__ float    d_Hbuf[2 * Bsz * Hsz];           // [cell][b][j]
static __device__ uint32_t d_Wp_hi[4194304];  // W frags: [blk128][ks64][mw4][lane32][w4]
static __device__ uint32_t d_Wp_lo[4194304];
static __device__ uint32_t d_Tp_hi[32768];    // T frags: [nw2][ks64][lane32][8 words]
static __device__ uint32_t d_Tp_lo[32768];
static __device__ unsigned g_bar, g_gen;

// ------------------------------- helpers -----------------------------------------
#define MMA16816(c, a0, a1, a2, a3, b0, b1) \
    asm volatile("mma.sync.aligned.m16n8k16.row.col.f32.bf16.bf16.f32 " \
        "{%0,%1,%2,%3}, {%4,%5,%6,%7}, {%8,%9}, {%0,%1,%2,%3};" \
        : "+f"((c)[0]), "+f"((c)[1]), "+f"((c)[2]), "+f"((c)[3]) \
        : "r"(a0), "r"(a1), "r"(a2), "r"(a3), "r"(b0), "r"(b1))

__device__ __forceinline__ void gridbar(unsigned& gen) {
    __syncthreads();
    if (threadIdx.x == 0) {
        __threadfence();
        if (atomicAdd(&g_bar, 1u) == NBLK - 1) {
            atomicExch(&g_bar, 0u);
            __threadfence();
            atomicAdd(&g_gen, 1u);
        } else {
            while (atomicAdd(&g_gen, 0u) == gen) { }
        }
        __threadfence();
    }
    __syncthreads();
    gen++;
}

__device__ __forceinline__ uint32_t pack_hi(float v0, float v1) {
    __nv_bfloat16 h0 = __float2bfloat16(v0), h1 = __float2bfloat16(v1);
    return (uint32_t)__bfloat16_as_ushort(h0) | ((uint32_t)__bfloat16_as_ushort(h1) << 16);
}
__device__ __forceinline__ uint32_t pack_lo(float v0, float v1) {
    __nv_bfloat16 h0 = __float2bfloat16(v0), h1 = __float2bfloat16(v1);
    float r0 = v0 - __bfloat162float(h0), r1 = v1 - __bfloat162float(h1);
    __nv_bfloat16 l0 = __float2bfloat16(r0), l1 = __float2bfloat16(r1);
    return (uint32_t)__bfloat16_as_ushort(l0) | ((uint32_t)__bfloat16_as_ushort(l1) << 16);
}

// =================================================================================
// pack: Whh -> bf16 hi/lo A-fragments.
// word idx: w=idx&3, lane=(idx>>2)&31, mw=(idx>>7)&3, ks=(idx>>9)&63, blk=idx>>15
// A frag (m16n8k16 row-major): g=lane>>2, t=lane&3;
//   w0:(g,t2) w1:(g+8,t2) w2:(g,t2+8) w3:(g+8,t2+8), each word = 2 adjacent k.
// block blk: cell=blk>>6, units u0=(blk&63)*16 .. +15; row m = mw(gate)*16 + lr.
// =================================================================================
__global__ void __launch_bounds__(256) pack_whh_kernel(
    const float* __restrict__ WhhF, const float* __restrict__ WhhR)
{
    unsigned idx = blockIdx.x * 256u + threadIdx.x;        // < 4194304
    int w = idx & 3, lane = (idx >> 2) & 31, mw = (idx >> 7) & 3;
    int ks = (idx >> 9) & 63, blk = idx >> 15;
    int g = lane >> 2, t = lane & 3;
    int lr = g + 8 * (w & 1);                              // local row 0..15
    int u = ((blk & 63) << 4) + lr;                        // global unit
    int k = ks * 16 + t * 2 + 8 * (w >> 1);
    const float* W = (blk >> 6) ? WhhR : WhhF;
    float2 v = *reinterpret_cast<const float2*>(&W[((size_t)mw * Hsz + u) * Hsz + k]);
    d_Wp_hi[idx] = pack_hi(v.x, v.y);
    d_Wp_lo[idx] = pack_lo(v.x, v.y);
}

// =================================================================================
// Phase A (fp32 SIMT, unchanged): Xg[s,col,b] = x@Wih_cat.T + biases
// =================================================================================
__global__ void __launch_bounds__(256) phaseA_kernel(
    const float* __restrict__ x,
    const float* __restrict__ WihF, const float* __restrict__ WihR,
    const float* __restrict__ bihF, const float* __restrict__ bhhF,
    const float* __restrict__ bihR, const float* __restrict__ bhhR)
{
    const int s = blockIdx.y, col0 = blockIdx.x << 6, tid = threadIdx.x;
    const int tx = tid & 15, ty = tid >> 4, lb = tid >> 2, lk = (tid & 3) << 2;
    __shared__ float xs[16][68], ws[16][68];

    const int colL = col0 + lb;
    const float* wrow = (colL < H4) ? (WihF + (size_t)colL * INP)
                                    : (WihR + (size_t)(colL - H4) * INP);
    const float* xrow = x + ((size_t)lb * Ssz + s) * INP;

    float acc[4][4];
#pragma unroll
    for (int j = 0; j < 4; ++j)
#pragma unroll
        for (int i = 0; i < 4; ++i) acc[j][i] = 0.f;

    float4 tX = *reinterpret_cast<const float4*>(xrow + lk);
    float4 tW = *reinterpret_cast<const float4*>(wrow + lk);
    for (int k0 = 0; k0 < INP; k0 += 16) {
        xs[lk+0][lb] = tX.x; xs[lk+1][lb] = tX.y; xs[lk+2][lb] = tX.z; xs[lk+3][lb] = tX.w;
        ws[lk+0][lb] = tW.x; ws[lk+1][lb] = tW.y; ws[lk+2][lb] = tW.z; ws[lk+3][lb] = tW.w;
        __syncthreads();
        if (k0 + 16 < INP) {
            tX = *reinterpret_cast<const float4*>(xrow + k0 + 16 + lk);
            tW = *reinterpret_cast<const float4*>(wrow + k0 + 16 + lk);
        }
#pragma unroll
        for (int kk = 0; kk < 16; ++kk) {
            float4 bv = *reinterpret_cast<const float4*>(&xs[kk][ty << 2]);
            float4 wv = *reinterpret_cast<const float4*>(&ws[kk][tx << 2]);
            const float bb[4] = {bv.x, bv.y, bv.z, bv.w};
            const float ww[4] = {wv.x, wv.y, wv.z, wv.w};
#pragma unroll
            for (int j = 0; j < 4; ++j)
#pragma unroll
                for (int i = 0; i < 4; ++i) acc[j][i] = fmaf(ww[j], bb[i], acc[j][i]);
        }
        __syncthreads();
    }
#pragma unroll
    for (int j = 0; j < 4; ++j) {
        int col = col0 + (tx << 2) + j;
        float bias = (col < H4) ? (bihF[col] + bhhF[col])
                                : (bihR[col - H4] + bhhR[col - H4]);
        float4 v = make_float4(acc[j][0] + bias, acc[j][1] + bias,
                               acc[j][2] + bias, acc[j][3] + bias);
        *reinterpret_cast<float4*>(&d_Xg[((size_t)s * Gsz + col) * Bsz + (ty << 2)]) = v;
    }
}

// =================================================================================
// Phase B: 128 persistent blocks x 256 thr (8 warps: mw=wid&3, nw=wid>>2).
// Per step: HMMA bf16x3 GEMM (64 rows x 64 batches x K1024) -> smem -> LSTM ->
// barrier -> attention (blocks 0..63) -> T repack -> barrier.
// =================================================================================
__global__ void __launch_bounds__(256, 1) phaseB_kernel(
    const float* __restrict__ WaFw, const float* __restrict__ WaFb,
    const float* __restrict__ WaRw, const float* __restrict__ WaRb,
    const float* __restrict__ Fw,   const float* __restrict__ Fb,
    const float* __restrict__ Rw,   const float* __restrict__ Rb,
    float* __restrict__ out)
{
    const int tid = threadIdx.x, blk = blockIdx.x;
    const int cell = blk >> 6, u0 = (blk & 63) << 4;
    const int wid = tid >> 5, lane = tid & 31;
    const int mw = wid & 3, nw = wid >> 2;
    const int g = lane >> 2, t = lane & 3;

    __shared__ float gsm[64][68];     // raw D: [row m][batch b]
    __shared__ float hsh[2 * Hsz];
    __shared__ float lg[256];
    __shared__ float itm[64];
    __shared__ unsigned s_gen;

    // zero initial T fragments (exactly 32768 words; grid has 32768 threads)
    {
        unsigned gi = blk * 256u + tid;
        if (gi < 32768) { __stcg(&d_Tp_hi[gi], 0u); __stcg(&d_Tp_lo[gi], 0u); }
    }
    if (tid == 0) s_gen = atomicAdd(&g_gen, 0u);
    __syncthreads();
    unsigned gen = s_gen;
    gridbar(gen);

    // fixed per-thread fragment pointers (A: +128 uint4/ks, B: +64 uint4/ks)
    const uint4* pAh0 = (const uint4*)d_Wp_hi + (size_t)blk * 8192 + mw * 32 + lane;
    const uint4* pAl0 = (const uint4*)d_Wp_lo + (size_t)blk * 8192 + mw * 32 + lane;
    const uint4* pBh0 = (const uint4*)d_Tp_hi + nw * 4096 + lane * 2;
    const uint4* pBl0 = (const uint4*)d_Tp_lo + nw * 4096 + lane * 2;

    const int gu = tid >> 4, gb = (tid & 15) << 2;   // gate-math: unit gu, batches gb..gb+3
    float cst[4] = {0.f, 0.f, 0.f, 0.f};

    float* outAF = out + (size_t)Bsz * Ssz * Hsz;
    float* outAR = outAF + (size_t)Bsz * Ssz * NS;

    for (int s = 0; s < Ssz; ++s) {
        // ---------------- recurrent GEMM (bf16x3 HMMA) --------------------------
        float acc[4][4];
#pragma unroll
        for (int n = 0; n < 4; ++n)
#pragma unroll
            for (int i = 0; i < 4; ++i) acc[n][i] = 0.f;

        const uint4* pAh = pAh0; const uint4* pAl = pAl0;
        const uint4* pBh = pBh0; const uint4* pBl = pBl0;
        uint4 cAh = __ldg(pAh),  cAl = __ldg(pAl);
        uint4 cB0 = __ldcg(pBh), cB1 = __ldcg(pBh + 1);
        uint4 cB2 = __ldcg(pBl), cB3 = __ldcg(pBl + 1);

#pragma unroll 4
        for (int ks = 0; ks < 64; ++ks) {
            uint4 nAh, nAl, nB0, nB1, nB2, nB3;
            if (ks < 63) {
                pAh += 128; pAl += 128; pBh += 64; pBl += 64;
                nAh = __ldg(pAh);  nAl = __ldg(pAl);
                nB0 = __ldcg(pBh); nB1 = __ldcg(pBh + 1);
                nB2 = __ldcg(pBl); nB3 = __ldcg(pBl + 1);
            }
            // nt0
            MMA16816(acc[0], cAh.x, cAh.y, cAh.z, cAh.w, cB0.x, cB0.y);
            MMA16816(acc[0], cAh.x, cAh.y, cAh.z, cAh.w, cB2.x, cB2.y);
            MMA16816(acc[0], cAl.x, cAl.y, cAl.z, cAl.w, cB0.x, cB0.y);
            // nt1
            MMA16816(acc[1], cAh.x, cAh.y, cAh.z, cAh.w, cB0.z, cB0.w);
            MMA16816(acc[1], cAh.x, cAh.y, cAh.z, cAh.w, cB2.z, cB2.w);
            MMA16816(acc[1], cAl.x, cAl.y, cAl.z, cAl.w, cB0.z, cB0.w);
            // nt2
            MMA16816(acc[2], cAh.x, cAh.y, cAh.z, cAh.w, cB1.x, cB1.y);
            MMA16816(acc[2], cAh.x, cAh.y, cAh.z, cAh.w, cB3.x, cB3.y);
            MMA16816(acc[2], cAl.x, cAl.y, cAl.z, cAl.w, cB1.x, cB1.y);
            // nt3
            MMA16816(acc[3], cAh.x, cAh.y, cAh.z, cAh.w, cB1.z, cB1.w);
            MMA16816(acc[3], cAh.x, cAh.y, cAh.z, cAh.w, cB3.z, cB3.w);
            MMA16816(acc[3], cAl.x, cAl.y, cAl.z, cAl.w, cB1.z, cB1.w);
            cAh = nAh; cAl = nAl; cB0 = nB0; cB1 = nB1; cB2 = nB2; cB3 = nB3;
        }

        // store fragments: rows mw*16+{g,g+8}, cols nw*32 + nt*8 + t*2 +{0,1}
#pragma unroll
        for (int nt = 0; nt < 4; ++nt) {
            int col = nw * 32 + nt * 8 + t * 2;
            float* r0 = &gsm[mw * 16 + g][col];
            r0[0] = acc[nt][0]; r0[1] = acc[nt][1];
            float* r1 = &gsm[mw * 16 + g + 8][col];
            r1[0] = acc[nt][2]; r1[1] = acc[nt][3];
        }
        __syncthreads();

        // ---------------- gates: unit gu, batches gb..gb+3 ----------------------
        {
            float4 xg[4];
#pragma unroll
            for (int gate = 0; gate < 4; ++gate) {
                size_t col = (size_t)cell * H4 + (size_t)gate * Hsz + u0 + gu;
                xg[gate] = *reinterpret_cast<const float4*>(
                    &d_Xg[((size_t)s * Gsz + col) * Bsz + gb]);
            }
#pragma unroll
            for (int i = 0; i < 4; ++i) {
                int b = gb + i;
                float iv = gsm[      gu][b] + reinterpret_cast<const float*>(&xg[0])[i];
                float fv = gsm[16 + gu][b] + reinterpret_cast<const float*>(&xg[1])[i];
                float gv = gsm[32 + gu][b] + reinterpret_cast<const float*>(&xg[2])[i];
                float ov = gsm[48 + gu][b] + reinterpret_cast<const float*>(&xg[3])[i];
                float si = 1.f / (1.f + __expf(-iv));
                float sf = 1.f / (1.f + __expf(-fv));
                float so = 1.f / (1.f + __expf(-ov));
                float c2 = sf * cst[i] + si * tanhf(gv);
                cst[i] = c2;
                __stcg(&d_Hbuf[((size_t)cell * Bsz + b) * Hsz + u0 + gu], so * tanhf(c2));
            }
        }

        gridbar(gen);   // h complete

        // ---------------- attention: block b (<64) handles batch b -------------
        if (blk < Bsz) {
            const int b = blk;
            for (int i = tid; i < 2 * Hsz; i += 256)
                hsh[i] = __ldcg(&d_Hbuf[((size_t)(i >> 10) * Bsz + b) * Hsz + (i & (Hsz - 1))]);
            __syncthreads();

            for (int r = wid; r < NS + NR; r += 8) {
                const float* wr; const float* hh; float bias;
                if (r < NS) { wr = WaFw + (size_t)r * Hsz;        hh = hsh;       bias = WaFb[r]; }
                else        { wr = WaRw + (size_t)(r - NS) * Hsz; hh = hsh + Hsz; bias = WaRb[r - NS]; }
                float sum = 0.f;
                for (int k = lane; k < Hsz; k += 32) sum = fmaf(__ldg(&wr[k]), hh[k], sum);
#pragma unroll
                for (int off = 16; off; off >>= 1) sum += __shfl_down_sync(0xffffffffu, sum, off);
                if (lane == 0) lg[r] = sum + bias;
            }
            __syncthreads();

            if (wid == 0) {
                float m = -1e30f;
                for (int n = lane; n < NS; n += 32) m = fmaxf(m, lg[n]);
#pragma unroll
                for (int off = 16; off; off >>= 1) m = fmaxf(m, __shfl_xor_sync(0xffffffffu, m, off));
                float ssum = 0.f;
                for (int n = lane; n < NS; n += 32) { float e = __expf(lg[n] - m); lg[n] = e; ssum += e; }
#pragma unroll
                for (int off = 16; off; off >>= 1) ssum += __shfl_xor_sync(0xffffffffu, ssum, off);
                float inv = 1.f / ssum;
                for (int n = lane; n < NS; n += 32) {
                    float a = lg[n] * inv; lg[n] = a;
                    outAF[((size_t)b * Ssz + s) * NS + n] = a;
                }
            } else if (wid == 1) {
                float m = -1e30f;
                for (int n = lane; n < NR; n += 32) m = fmaxf(m, lg[NS + n]);
#pragma unroll
                for (int off = 16; off; off >>= 1) m = fmaxf(m, __shfl_xor_sync(0xffffffffu, m, off));
                float ssum = 0.f;
                for (int n = lane; n < NR; n += 32) { float e = __expf(lg[NS + n] - m); lg[NS + n] = e; ssum += e; }
#pragma unroll
                for (int off = 16; off; off >>= 1) ssum += __shfl_xor_sync(0xffffffffu, ssum, off);
                float inv = 1.f / ssum;
                for (int n = lane; n < NR; n += 32) {
                    float a = lg[NS + n] * inv; lg[NS + n] = a;
                    outAR[((size_t)b * Ssz + s) * NR + n] = a;
                }
            }
            __syncthreads();

            if (tid < 32) {
                float sum = Fb[tid];
                for (int n = 0; n < NS; ++n) sum = fmaf(lg[n], __ldg(&Fw[tid * NS + n]), sum);
                itm[tid] = sum;
            } else if (tid < 64) {
                int d = tid - 32;
                float sum = Rb[d];
                for (int n = 0; n < NR; ++n) sum = fmaf(lg[NS + n], __ldg(&Rw[d * NR + n]), sum);
                itm[32 + d] = sum;
            }
            __syncthreads();

            // T row b -> main output + bf16 hi/lo B-fragments
            const int bnw = b >> 5, bnt = (b >> 3) & 3, bn = b & 7;
            for (int idx = tid; idx < 512; idx += 256) {
                int ks = idx >> 3, q = idx & 3, reg = (idx >> 2) & 1;
                int k0 = ks * 16 + reg * 8 + q * 2;
                float v0 = itm[k0 >> 5] * itm[32 + (k0 & 31)];
                float v1 = itm[(k0 + 1) >> 5] * itm[32 + ((k0 + 1) & 31)];
                out[((size_t)b * Ssz + s) * Hsz + k0]     = v0;
                out[((size_t)b * Ssz + s) * Hsz + k0 + 1] = v1;
                int fl = bn * 4 + q;
                int word = ((bnw * 64 + ks) * 32 + fl) * 8 + bnt * 2 + reg;
                __stcg(&d_Tp_hi[word], pack_hi(v0, v1));
                __stcg(&d_Tp_lo[word], pack_lo(v0, v1));
            }
        }

        gridbar(gen);   // T fragments complete for next step
    }
}

// =================================================================================
extern "C" void kernel_launch(void* const* d_in, const int* in_sizes, int n_in,
                              void* d_out, int out_size) {
    (void)in_sizes; (void)n_in; (void)out_size;
    const float* x    = (const float*)d_in[0];
    const float* WihF = (const float*)d_in[1];
    const float* WhhF = (const float*)d_in[2];
    const float* bihF = (const float*)d_in[3];
    const float* bhhF = (const float*)d_in[4];
    const float* WihR = (const float*)d_in[5];
    const float* WhhR = (const float*)d_in[6];
    const float* bihR = (const float*)d_in[7];
    const float* bhhR = (const float*)d_in[8];
    const float* WaFw = (const float*)d_in[9];
    const float* WaFb = (const float*)d_in[10];
    const float* WaRw = (const float*)d_in[11];
    const float* WaRb = (const float*)d_in[12];
    const float* Fw   = (const float*)d_in[13];
    const float* Fb   = (const float*)d_in[14];
    const float* Rw   = (const float*)d_in[15];
    const float* Rb   = (const float*)d_in[16];
    float* out = (float*)d_out;

    pack_whh_kernel<<<16384, 256>>>(WhhF, WhhR);
    phaseA_kernel<<<dim3(128, 256), 256>>>(x, WihF, WihR, bihF, bhhF, bihR, bhhR);
    phaseB_kernel<<<NBLK, 256>>>(WaFw, WaFb, WaRw, WaRb, Fw, Fb, Rw, Rb, out);
}

// round 5
// speedup vs baseline: 1.7419x; 1.1999x over previous
#include <cuda_runtime.h>
#include <cuda_bf16.h>
#include <cstdint>
#include <math.h>

#define Bsz  64
#define Ssz  256
#define INP  400
#define Hsz  1024
#define H4   4096
#define Gsz  8192
#define NS   150
#define NR   50
#define NBLK 128

// ------------------------------- device scratch ---------------------------------
static __device__ float    d_Xg[(size_t)Ssz * Gsz * Bsz];   // [s][col(8192)][b]
static __device__ float    d_Hbuf[2 * Bsz * Hsz];           // [cell][b][j]
static __device__ uint32_t d_Wp_hi[4194304];   // Whh A-frags [blk128][ks64][mw4][lane][4]
static __device__ uint32_t d_Wp_lo[4194304];
static __device__ uint32_t d_Tp_hi[32768];     // T B-frags [nw2][ks64][lane][8]
static __device__ uint32_t d_Tp_lo[32768];
static __device__ uint32_t d_WIp_hi[6553600];  // Wih A-frags [ct64][ks25][mw8][lane][4]
static __device__ uint32_t d_WIp_lo[6553600];
static __device__ uint32_t d_XIp_hi[3276800];  // x B-frags [s256][ks25][lane][16]
static __device__ uint32_t d_XIp_lo[3276800];
static __device__ unsigned g_bar, g_gen;

// ------------------------------- helpers -----------------------------------------
#define MMA16816(c, a0, a1, a2, a3, b0, b1) \
    asm volatile("mma.sync.aligned.m16n8k16.row.col.f32.bf16.bf16.f32 " \
        "{%0,%1,%2,%3}, {%4,%5,%6,%7}, {%8,%9}, {%0,%1,%2,%3};" \
        : "+f"((c)[0]), "+f"((c)[1]), "+f"((c)[2]), "+f"((c)[3]) \
        : "r"(a0), "r"(a1), "r"(a2), "r"(a3), "r"(b0), "r"(b1))

__device__ __forceinline__ void gridbar(unsigned& gen) {
    __syncthreads();
    if (threadIdx.x == 0) {
        __threadfence();
        if (atomicAdd(&g_bar, 1u) == NBLK - 1) {
            atomicExch(&g_bar, 0u);
            __threadfence();
            atomicAdd(&g_gen, 1u);
        } else {
            while (*(volatile unsigned*)&g_gen == gen) __nanosleep(64);
        }
        __threadfence();   // acquire + L1 invalidate (CCTL.IVALL at gpu scope)
    }
    __syncthreads();
    gen++;
}

__device__ __forceinline__ uint32_t pack_hi(float v0, float v1) {
    __nv_bfloat16 h0 = __float2bfloat16(v0), h1 = __float2bfloat16(v1);
    return (uint32_t)__bfloat16_as_ushort(h0) | ((uint32_t)__bfloat16_as_ushort(h1) << 16);
}
__device__ __forceinline__ uint32_t pack_lo(float v0, float v1) {
    __nv_bfloat16 h0 = __float2bfloat16(v0), h1 = __float2bfloat16(v1);
    float r0 = v0 - __bfloat162float(h0), r1 = v1 - __bfloat162float(h1);
    __nv_bfloat16 l0 = __float2bfloat16(r0), l1 = __float2bfloat16(r1);
    return (uint32_t)__bfloat16_as_ushort(l0) | ((uint32_t)__bfloat16_as_ushort(l1) << 16);
}

// =================================================================================
// pack Whh -> A-fragments (proven layout from R4)
// =================================================================================
__global__ void __launch_bounds__(256) pack_whh_kernel(
    const float* __restrict__ WhhF, const float* __restrict__ WhhR)
{
    unsigned idx = blockIdx.x * 256u + threadIdx.x;        // < 4194304
    int w = idx & 3, lane = (idx >> 2) & 31, mw = (idx >> 7) & 3;
    int ks = (idx >> 9) & 63, blk = idx >> 15;
    int g = lane >> 2, t = lane & 3;
    int lr = g + 8 * (w & 1);
    int u = ((blk & 63) << 4) + lr;
    int k = ks * 16 + t * 2 + 8 * (w >> 1);
    const float* W = (blk >> 6) ? WhhR : WhhF;
    float2 v = *reinterpret_cast<const float2*>(&W[((size_t)mw * Hsz + u) * Hsz + k]);
    d_Wp_hi[idx] = pack_hi(v.x, v.y);
    d_Wp_lo[idx] = pack_lo(v.x, v.y);
}

// =================================================================================
// pack Wih (cat) -> A-fragments: col = ct*128 + mw*16 + lr, K=400 (25 ks-tiles)
// =================================================================================
__global__ void __launch_bounds__(256) pack_wih_kernel(
    const float* __restrict__ WihF, const float* __restrict__ WihR)
{
    unsigned idx = blockIdx.x * 256u + threadIdx.x;        // < 6553600
    int w = idx & 3, lane = (idx >> 2) & 31, mw = (idx >> 7) & 7;
    unsigned rest = idx >> 10;
    int ks = rest % 25, ct = rest / 25;
    int g = lane >> 2, t = lane & 3;
    int lr = g + 8 * (w & 1);
    int col = ct * 128 + mw * 16 + lr;
    int k = ks * 16 + t * 2 + 8 * (w >> 1);
    const float* W = (col < H4) ? (WihF + (size_t)col * INP)
                                : (WihR + (size_t)(col - H4) * INP);
    float2 v = *reinterpret_cast<const float2*>(&W[k]);
    d_WIp_hi[idx] = pack_hi(v.x, v.y);
    d_WIp_lo[idx] = pack_lo(v.x, v.y);
}

// =================================================================================
// pack x -> B-fragments: [s][ks25][lane][nt*2+reg], n = batch = nt*8 + (lane>>2)
// =================================================================================
__global__ void __launch_bounds__(256) pack_x_kernel(const float* __restrict__ x)
{
    unsigned idx = blockIdx.x * 256u + threadIdx.x;        // < 3276800
    int w16 = idx & 15, lane = (idx >> 4) & 31;
    unsigned rest = idx >> 9;
    int ks = rest % 25, s = rest / 25;
    int nt = w16 >> 1, reg = w16 & 1;
    int b = nt * 8 + (lane >> 2);
    int k = ks * 16 + reg * 8 + (lane & 3) * 2;
    float2 v = *reinterpret_cast<const float2*>(&x[((size_t)b * Ssz + s) * INP + k]);
    d_XIp_hi[idx] = pack_hi(v.x, v.y);
    d_XIp_lo[idx] = pack_lo(v.x, v.y);
}

// =================================================================================
// Phase A via HMMA bf16x3: block (s, ct): 128 cols x 64 batches, K=400.
// warp wid = row-tile (16 rows); 8 n-tiles of 8 batches.
// =================================================================================
__global__ void __launch_bounds__(256, 2) phaseA_mma_kernel(
    const float* __restrict__ bihF, const float* __restrict__ bhhF,
    const float* __restrict__ bihR, const float* __restrict__ bhhR)
{
    const int s = blockIdx.x, ct = blockIdx.y;
    const int tid = threadIdx.x, wid = tid >> 5, lane = tid & 31;
    const int g = lane >> 2, t = lane & 3;

    float acc[8][4];
#pragma unroll
    for (int n = 0; n < 8; ++n)
#pragma unroll
        for (int i = 0; i < 4; ++i) acc[n][i] = 0.f;

    const uint4* pAh = (const uint4*)d_WIp_hi + ((size_t)(ct * 25) * 8 + wid) * 32 + lane;
    const uint4* pAl = (const uint4*)d_WIp_lo + ((size_t)(ct * 25) * 8 + wid) * 32 + lane;
    const uint4* pBh = (const uint4*)d_XIp_hi + ((size_t)(s * 25) * 32 + lane) * 4;
    const uint4* pBl = (const uint4*)d_XIp_lo + ((size_t)(s * 25) * 32 + lane) * 4;

    for (int ks = 0; ks < 25; ++ks) {
        uint32_t ah[4], al[4], bh[16], bl[16];
        *(uint4*)&ah[0] = __ldg(pAh);
        *(uint4*)&al[0] = __ldg(pAl);
#pragma unroll
        for (int j = 0; j < 4; ++j) {
            *(uint4*)&bh[4 * j] = __ldg(pBh + j);
            *(uint4*)&bl[4 * j] = __ldg(pBl + j);
        }
        pAh += 256; pAl += 256; pBh += 128; pBl += 128;
        // pass 0: Ahi x Bhi
#pragma unroll
        for (int nt = 0; nt < 8; ++nt)
            MMA16816(acc[nt], ah[0], ah[1], ah[2], ah[3], bh[nt * 2], bh[nt * 2 + 1]);
        // pass 1: Ahi x Blo
#pragma unroll
        for (int nt = 0; nt < 8; ++nt)
            MMA16816(acc[nt], ah[0], ah[1], ah[2], ah[3], bl[nt * 2], bl[nt * 2 + 1]);
        // pass 2: Alo x Bhi
#pragma unroll
        for (int nt = 0; nt < 8; ++nt)
            MMA16816(acc[nt], al[0], al[1], al[2], al[3], bh[nt * 2], bh[nt * 2 + 1]);
    }

    const int cg0 = ct * 128 + wid * 16 + g, cg1 = cg0 + 8;
    float bs0 = (cg0 < H4) ? (bihF[cg0] + bhhF[cg0]) : (bihR[cg0 - H4] + bhhR[cg0 - H4]);
    float bs1 = (cg1 < H4) ? (bihF[cg1] + bhhF[cg1]) : (bihR[cg1 - H4] + bhhR[cg1 - H4]);
    float* base0 = &d_Xg[((size_t)s * Gsz + cg0) * Bsz];
    float* base1 = &d_Xg[((size_t)s * Gsz + cg1) * Bsz];
#pragma unroll
    for (int nt = 0; nt < 8; ++nt) {
        int n0 = nt * 8 + t * 2;
        *(float2*)&base0[n0] = make_float2(acc[nt][0] + bs0, acc[nt][1] + bs0);
        *(float2*)&base1[n0] = make_float2(acc[nt][2] + bs1, acc[nt][3] + bs1);
    }
}

// =================================================================================
// Phase B: 128 persistent blocks x 256 thr (mw=wid&3, nw=wid>>2).
// =================================================================================
__global__ void __launch_bounds__(256, 1) phaseB_kernel(
    const float* __restrict__ WaFw, const float* __restrict__ WaFb,
    const float* __restrict__ WaRw, const float* __restrict__ WaRb,
    const float* __restrict__ Fw,   const float* __restrict__ Fb,
    const float* __restrict__ Rw,   const float* __restrict__ Rb,
    float* __restrict__ out)
{
    const int tid = threadIdx.x, blk = blockIdx.x;
    const int cell = blk >> 6, u0 = (blk & 63) << 4;
    const int wid = tid >> 5, lane = tid & 31;
    const int mw = wid & 3, nw = wid >> 2;
    const int g = lane >> 2, t = lane & 3;

    __shared__ float gsm[64][68];
    __shared__ float hsh[2 * Hsz];
    __shared__ float lg[256];
    __shared__ float itm[64];
    __shared__ unsigned s_gen;

    {
        unsigned gi = blk * 256u + tid;
        if (gi < 32768) { __stcg(&d_Tp_hi[gi], 0u); __stcg(&d_Tp_lo[gi], 0u); }
    }
    if (tid == 0) s_gen = atomicAdd(&g_gen, 0u);
    __syncthreads();
    unsigned gen = s_gen;
    gridbar(gen);

    const uint4* pAh0 = (const uint4*)d_Wp_hi + (size_t)blk * 8192 + mw * 32 + lane;
    const uint4* pAl0 = (const uint4*)d_Wp_lo + (size_t)blk * 8192 + mw * 32 + lane;
    const uint4* pBh0 = (const uint4*)d_Tp_hi + nw * 4096 + lane * 2;
    const uint4* pBl0 = (const uint4*)d_Tp_lo + nw * 4096 + lane * 2;

    const int gu = tid >> 4, gb = (tid & 15) << 2;
    float cst[4] = {0.f, 0.f, 0.f, 0.f};

    float* outAF = out + (size_t)Bsz * Ssz * Hsz;
    float* outAR = outAF + (size_t)Bsz * Ssz * NS;

    for (int s = 0; s < Ssz; ++s) {
        // ---------------- recurrent GEMM (bf16x3 HMMA) --------------------------
        float acc[4][4];
#pragma unroll
        for (int n = 0; n < 4; ++n)
#pragma unroll
            for (int i = 0; i < 4; ++i) acc[n][i] = 0.f;

        const uint4* pAh = pAh0; const uint4* pAl = pAl0;
        const uint4* pBh = pBh0; const uint4* pBl = pBl0;
        uint4 cAh = __ldg(pAh), cAl = __ldg(pAl);
        uint4 cB0 = pBh[0], cB1 = pBh[1];      // plain L1-cached loads (dedupe 4x)
        uint4 cB2 = pBl[0], cB3 = pBl[1];

#pragma unroll 4
        for (int ks = 0; ks < 64; ++ks) {
            uint4 nAh, nAl, nB0, nB1, nB2, nB3;
            if (ks < 63) {
                pAh += 128; pAl += 128; pBh += 64; pBl += 64;
                nAh = __ldg(pAh); nAl = __ldg(pAl);
                nB0 = pBh[0]; nB1 = pBh[1];
                nB2 = pBl[0]; nB3 = pBl[1];
            }
            // pass 0: Ahi x Bhi (RAW distance 4)
            MMA16816(acc[0], cAh.x, cAh.y, cAh.z, cAh.w, cB0.x, cB0.y);
            MMA16816(acc[1], cAh.x, cAh.y, cAh.z, cAh.w, cB0.z, cB0.w);
            MMA16816(acc[2], cAh.x, cAh.y, cAh.z, cAh.w, cB1.x, cB1.y);
            MMA16816(acc[3], cAh.x, cAh.y, cAh.z, cAh.w, cB1.z, cB1.w);
            // pass 1: Ahi x Blo
            MMA16816(acc[0], cAh.x, cAh.y, cAh.z, cAh.w, cB2.x, cB2.y);
            MMA16816(acc[1], cAh.x, cAh.y, cAh.z, cAh.w, cB2.z, cB2.w);
            MMA16816(acc[2], cAh.x, cAh.y, cAh.z, cAh.w, cB3.x, cB3.y);
            MMA16816(acc[3], cAh.x, cAh.y, cAh.z, cAh.w, cB3.z, cB3.w);
            // pass 2: Alo x Bhi
            MMA16816(acc[0], cAl.x, cAl.y, cAl.z, cAl.w, cB0.x, cB0.y);
            MMA16816(acc[1], cAl.x, cAl.y, cAl.z, cAl.w, cB0.z, cB0.w);
            MMA16816(acc[2], cAl.x, cAl.y, cAl.z, cAl.w, cB1.x, cB1.y);
            MMA16816(acc[3], cAl.x, cAl.y, cAl.z, cAl.w, cB1.z, cB1.w);
            cAh = nAh; cAl = nAl; cB0 = nB0; cB1 = nB1; cB2 = nB2; cB3 = nB3;
        }

#pragma unroll
        for (int nt = 0; nt < 4; ++nt) {
            int col = nw * 32 + nt * 8 + t * 2;
            float* r0 = &gsm[mw * 16 + g][col];
            r0[0] = acc[nt][0]; r0[1] = acc[nt][1];
            float* r1 = &gsm[mw * 16 + g + 8][col];
            r1[0] = acc[nt][2]; r1[1] = acc[nt][3];
        }
        __syncthreads();

        // ---------------- gates ------------------------------------------------
        {
            float4 xg[4];
#pragma unroll
            for (int gate = 0; gate < 4; ++gate) {
                size_t col = (size_t)cell * H4 + (size_t)gate * Hsz + u0 + gu;
                xg[gate] = *reinterpret_cast<const float4*>(
                    &d_Xg[((size_t)s * Gsz + col) * Bsz + gb]);
            }
#pragma unroll
            for (int i = 0; i < 4; ++i) {
                int b = gb + i;
                float iv = gsm[      gu][b] + reinterpret_cast<const float*>(&xg[0])[i];
                float fv = gsm[16 + gu][b] + reinterpret_cast<const float*>(&xg[1])[i];
                float gv = gsm[32 + gu][b] + reinterpret_cast<const float*>(&xg[2])[i];
                float ov = gsm[48 + gu][b] + reinterpret_cast<const float*>(&xg[3])[i];
                float si = 1.f / (1.f + __expf(-iv));
                float sf = 1.f / (1.f + __expf(-fv));
                float so = 1.f / (1.f + __expf(-ov));
                float c2 = sf * cst[i] + si * tanhf(gv);
                cst[i] = c2;
                __stcg(&d_Hbuf[((size_t)cell * Bsz + b) * Hsz + u0 + gu], so * tanhf(c2));
            }
        }

        gridbar(gen);   // h complete

        // ---------------- attention: block b (<64) handles batch b -------------
        if (blk < Bsz) {
            const int b = blk;
            for (int i = tid; i < 2 * Hsz; i += 256)
                hsh[i] = __ldcg(&d_Hbuf[((size_t)(i >> 10) * Bsz + b) * Hsz + (i & (Hsz - 1))]);
            __syncthreads();

            for (int r = wid; r < NS + NR; r += 8) {
                const float* wr; const float* hh; float bias;
                if (r < NS) { wr = WaFw + (size_t)r * Hsz;        hh = hsh;       bias = WaFb[r]; }
                else        { wr = WaRw + (size_t)(r - NS) * Hsz; hh = hsh + Hsz; bias = WaRb[r - NS]; }
                float sum = 0.f;
                for (int k = lane; k < Hsz; k += 32) sum = fmaf(__ldg(&wr[k]), hh[k], sum);
#pragma unroll
                for (int off = 16; off; off >>= 1) sum += __shfl_down_sync(0xffffffffu, sum, off);
                if (lane == 0) lg[r] = sum + bias;
            }
            __syncthreads();

            if (wid == 0) {
                float m = -1e30f;
                for (int n = lane; n < NS; n += 32) m = fmaxf(m, lg[n]);
#pragma unroll
                for (int off = 16; off; off >>= 1) m = fmaxf(m, __shfl_xor_sync(0xffffffffu, m, off));
                float ssum = 0.f;
                for (int n = lane; n < NS; n += 32) { float e = __expf(lg[n] - m); lg[n] = e; ssum += e; }
#pragma unroll
                for (int off = 16; off; off >>= 1) ssum += __shfl_xor_sync(0xffffffffu, ssum, off);
                float inv = 1.f / ssum;
                for (int n = lane; n < NS; n += 32) {
                    float a = lg[n] * inv; lg[n] = a;
                    outAF[((size_t)b * Ssz + s) * NS + n] = a;
                }
            } else if (wid == 1) {
                float m = -1e30f;
                for (int n = lane; n < NR; n += 32) m = fmaxf(m, lg[NS + n]);
#pragma unroll
                for (int off = 16; off; off >>= 1) m = fmaxf(m, __shfl_xor_sync(0xffffffffu, m, off));
                float ssum = 0.f;
                for (int n = lane; n < NR; n += 32) { float e = __expf(lg[NS + n] - m); lg[NS + n] = e; ssum += e; }
#pragma unroll
                for (int off = 16; off; off >>= 1) ssum += __shfl_xor_sync(0xffffffffu, ssum, off);
                float inv = 1.f / ssum;
                for (int n = lane; n < NR; n += 32) {
                    float a = lg[NS + n] * inv; lg[NS + n] = a;
                    outAR[((size_t)b * Ssz + s) * NR + n] = a;
                }
            }
            __syncthreads();

            if (tid < 32) {
                float sum = Fb[tid];
                for (int n = 0; n < NS; ++n) sum = fmaf(lg[n], __ldg(&Fw[tid * NS + n]), sum);
                itm[tid] = sum;
            } else if (tid < 64) {
                int d = tid - 32;
                float sum = Rb[d];
                for (int n = 0; n < NR; ++n) sum = fmaf(lg[NS + n], __ldg(&Rw[d * NR + n]), sum);
                itm[32 + d] = sum;
            }
            __syncthreads();

            const int bnw = b >> 5, bnt = (b >> 3) & 3, bn = b & 7;
            for (int idx = tid; idx < 512; idx += 256) {
                int ks = idx >> 3, q = idx & 3, reg = (idx >> 2) & 1;
                int k0 = ks * 16 + reg * 8 + q * 2;
                float v0 = itm[k0 >> 5] * itm[32 + (k0 & 31)];
                float v1 = itm[(k0 + 1) >> 5] * itm[32 + ((k0 + 1) & 31)];
                out[((size_t)b * Ssz + s) * Hsz + k0]     = v0;
                out[((size_t)b * Ssz + s) * Hsz + k0 + 1] = v1;
                int fl = bn * 4 + q;
                int word = ((bnw * 64 + ks) * 32 + fl) * 8 + bnt * 2 + reg;
                __stcg(&d_Tp_hi[word], pack_hi(v0, v1));
                __stcg(&d_Tp_lo[word], pack_lo(v0, v1));
            }
        }

        gridbar(gen);   // T fragments complete for next step
    }
}

// =================================================================================
extern "C" void kernel_launch(void* const* d_in, const int* in_sizes, int n_in,
                              void* d_out, int out_size) {
    (void)in_sizes; (void)n_in; (void)out_size;
    const float* x    = (const float*)d_in[0];
    const float* WihF = (const float*)d_in[1];
    const float* WhhF = (const float*)d_in[2];
    const float* bihF = (const float*)d_in[3];
    const float* bhhF = (const float*)d_in[4];
    const float* WihR = (const float*)d_in[5];
    const float* WhhR = (const float*)d_in[6];
    const float* bihR = (const float*)d_in[7];
    const float* bhhR = (const float*)d_in[8];
    const float* WaFw = (const float*)d_in[9];
    const float* WaFb = (const float*)d_in[10];
    const float* WaRw = (const float*)d_in[11];
    const float* WaRb = (const float*)d_in[12];
    const float* Fw   = (const float*)d_in[13];
    const float* Fb   = (const float*)d_in[14];
    const float* Rw   = (const float*)d_in[15];
    const float* Rb   = (const float*)d_in[16];
    float* out = (float*)d_out;

    pack_whh_kernel<<<16384, 256>>>(WhhF, WhhR);
    pack_wih_kernel<<<25600, 256>>>(WihF, WihR);
    pack_x_kernel<<<12800, 256>>>(x);
    phaseA_mma_kernel<<<dim3(256, 64), 256>>>(bihF, bhhF, bihR, bhhR);
    phaseB_kernel<<<NBLK, 256>>>(WaFw, WaFb, WaRw, WaRb, Fw, Fb, Rw, Rb, out);
}

// round 6
// speedup vs baseline: 2.3056x; 1.3236x over previous
#include <cuda_runtime.h>
#include <cuda_bf16.h>
#include <cstdint>
#include <math.h>

#define Bsz  64
#define Ssz  256
#define INP  400
#define Hsz  1024
#define H4   4096
#define Gsz  8192
#define NS   150
#define NR   50
#define NBLK 128

// ------------------------------- device scratch ---------------------------------
static __device__ float    d_Xg[(size_t)Ssz * Gsz * Bsz];   // [s][col(8192)][b]
static __device__ float    d_Hbuf[2 * Bsz * Hsz];           // [cell][b][j]
static __device__ uint32_t d_Wp_hi[4194304];   // Whh A-frags [blk128][ks64][mw4][lane][4]
static __device__ uint32_t d_Wp_lo[4194304];
static __device__ uint32_t d_Tp_hi[32768];     // T B-frags [nw2][ks64][lane][8]
static __device__ uint32_t d_Tp_lo[32768];
static __device__ uint32_t d_WIp_hi[6553600];  // Wih A-frags [ct64][ks25][mw8][lane][4]
static __device__ uint32_t d_WIp_lo[6553600];
static __device__ uint32_t d_XIp_hi[3276800];  // x B-frags [s256][ks25][lane][16]
static __device__ uint32_t d_XIp_lo[3276800];
static __device__ unsigned g_bar, g_gen;

// ------------------------------- helpers -----------------------------------------
#define MMA16816(c, a0, a1, a2, a3, b0, b1) \
    asm volatile("mma.sync.aligned.m16n8k16.row.col.f32.bf16.bf16.f32 " \
        "{%0,%1,%2,%3}, {%4,%5,%6,%7}, {%8,%9}, {%0,%1,%2,%3};" \
        : "+f"((c)[0]), "+f"((c)[1]), "+f"((c)[2]), "+f"((c)[3]) \
        : "r"(a0), "r"(a1), "r"(a2), "r"(a3), "r"(b0), "r"(b1))

__device__ __forceinline__ void gridbar(unsigned& gen) {
    __syncthreads();
    if (threadIdx.x == 0) {
        __threadfence();
        if (atomicAdd(&g_bar, 1u) == NBLK - 1) {
            atomicExch(&g_bar, 0u);
            __threadfence();
            atomicAdd(&g_gen, 1u);
        } else {
            while (*(volatile unsigned*)&g_gen == gen) { }
        }
        __threadfence();   // acquire + L1 invalidate (CCTL.IVALL at gpu scope)
    }
    __syncthreads();
    gen++;
}

__device__ __forceinline__ uint32_t pack_hi(float v0, float v1) {
    __nv_bfloat16 h0 = __float2bfloat16(v0), h1 = __float2bfloat16(v1);
    return (uint32_t)__bfloat16_as_ushort(h0) | ((uint32_t)__bfloat16_as_ushort(h1) << 16);
}
__device__ __forceinline__ uint32_t pack_lo(float v0, float v1) {
    __nv_bfloat16 h0 = __float2bfloat16(v0), h1 = __float2bfloat16(v1);
    float r0 = v0 - __bfloat162float(h0), r1 = v1 - __bfloat162float(h1);
    __nv_bfloat16 l0 = __float2bfloat16(r0), l1 = __float2bfloat16(r1);
    return (uint32_t)__bfloat16_as_ushort(l0) | ((uint32_t)__bfloat16_as_ushort(l1) << 16);
}

// =================================================================================
// pack Whh -> A-fragments
// =================================================================================
__global__ void __launch_bounds__(256) pack_whh_kernel(
    const float* __restrict__ WhhF, const float* __restrict__ WhhR)
{
    unsigned idx = blockIdx.x * 256u + threadIdx.x;        // < 4194304
    int w = idx & 3, lane = (idx >> 2) & 31, mw = (idx >> 7) & 3;
    int ks = (idx >> 9) & 63, blk = idx >> 15;
    int g = lane >> 2, t = lane & 3;
    int lr = g + 8 * (w & 1);
    int u = ((blk & 63) << 4) + lr;
    int k = ks * 16 + t * 2 + 8 * (w >> 1);
    const float* W = (blk >> 6) ? WhhR : WhhF;
    float2 v = *reinterpret_cast<const float2*>(&W[((size_t)mw * Hsz + u) * Hsz + k]);
    d_Wp_hi[idx] = pack_hi(v.x, v.y);
    d_Wp_lo[idx] = pack_lo(v.x, v.y);
}

// =================================================================================
// pack Wih (cat) -> A-fragments
// =================================================================================
__global__ void __launch_bounds__(256) pack_wih_kernel(
    const float* __restrict__ WihF, const float* __restrict__ WihR)
{
    unsigned idx = blockIdx.x * 256u + threadIdx.x;        // < 6553600
    int w = idx & 3, lane = (idx >> 2) & 31, mw = (idx >> 7) & 7;
    unsigned rest = idx >> 10;
    int ks = rest % 25, ct = rest / 25;
    int g = lane >> 2, t = lane & 3;
    int lr = g + 8 * (w & 1);
    int col = ct * 128 + mw * 16 + lr;
    int k = ks * 16 + t * 2 + 8 * (w >> 1);
    const float* W = (col < H4) ? (WihF + (size_t)col * INP)
                                : (WihR + (size_t)(col - H4) * INP);
    float2 v = *reinterpret_cast<const float2*>(&W[k]);
    d_WIp_hi[idx] = pack_hi(v.x, v.y);
    d_WIp_lo[idx] = pack_lo(v.x, v.y);
}

// =================================================================================
// pack x -> B-fragments
// =================================================================================
__global__ void __launch_bounds__(256) pack_x_kernel(const float* __restrict__ x)
{
    unsigned idx = blockIdx.x * 256u + threadIdx.x;        // < 3276800
    int w16 = idx & 15, lane = (idx >> 4) & 31;
    unsigned rest = idx >> 9;
    int ks = rest % 25, s = rest / 25;
    int nt = w16 >> 1, reg = w16 & 1;
    int b = nt * 8 + (lane >> 2);
    int k = ks * 16 + reg * 8 + (lane & 3) * 2;
    float2 v = *reinterpret_cast<const float2*>(&x[((size_t)b * Ssz + s) * INP + k]);
    d_XIp_hi[idx] = pack_hi(v.x, v.y);
    d_XIp_lo[idx] = pack_lo(v.x, v.y);
}

// =================================================================================
// Phase A via HMMA bf16x3 (unchanged from R5)
// =================================================================================
__global__ void __launch_bounds__(256, 2) phaseA_mma_kernel(
    const float* __restrict__ bihF, const float* __restrict__ bhhF,
    const float* __restrict__ bihR, const float* __restrict__ bhhR)
{
    const int s = blockIdx.x, ct = blockIdx.y;
    const int tid = threadIdx.x, wid = tid >> 5, lane = tid & 31;
    const int g = lane >> 2, t = lane & 3;

    float acc[8][4];
#pragma unroll
    for (int n = 0; n < 8; ++n)
#pragma unroll
        for (int i = 0; i < 4; ++i) acc[n][i] = 0.f;

    const uint4* pAh = (const uint4*)d_WIp_hi + ((size_t)(ct * 25) * 8 + wid) * 32 + lane;
    const uint4* pAl = (const uint4*)d_WIp_lo + ((size_t)(ct * 25) * 8 + wid) * 32 + lane;
    const uint4* pBh = (const uint4*)d_XIp_hi + ((size_t)(s * 25) * 32 + lane) * 4;
    const uint4* pBl = (const uint4*)d_XIp_lo + ((size_t)(s * 25) * 32 + lane) * 4;

    for (int ks = 0; ks < 25; ++ks) {
        uint32_t ah[4], al[4], bh[16], bl[16];
        *(uint4*)&ah[0] = __ldg(pAh);
        *(uint4*)&al[0] = __ldg(pAl);
#pragma unroll
        for (int j = 0; j < 4; ++j) {
            *(uint4*)&bh[4 * j] = __ldg(pBh + j);
            *(uint4*)&bl[4 * j] = __ldg(pBl + j);
        }
        pAh += 256; pAl += 256; pBh += 128; pBl += 128;
#pragma unroll
        for (int nt = 0; nt < 8; ++nt)
            MMA16816(acc[nt], ah[0], ah[1], ah[2], ah[3], bh[nt * 2], bh[nt * 2 + 1]);
#pragma unroll
        for (int nt = 0; nt < 8; ++nt)
            MMA16816(acc[nt], ah[0], ah[1], ah[2], ah[3], bl[nt * 2], bl[nt * 2 + 1]);
#pragma unroll
        for (int nt = 0; nt < 8; ++nt)
            MMA16816(acc[nt], al[0], al[1], al[2], al[3], bh[nt * 2], bh[nt * 2 + 1]);
    }

    const int cg0 = ct * 128 + wid * 16 + g, cg1 = cg0 + 8;
    float bs0 = (cg0 < H4) ? (bihF[cg0] + bhhF[cg0]) : (bihR[cg0 - H4] + bhhR[cg0 - H4]);
    float bs1 = (cg1 < H4) ? (bihF[cg1] + bhhF[cg1]) : (bihR[cg1 - H4] + bhhR[cg1 - H4]);
    float* base0 = &d_Xg[((size_t)s * Gsz + cg0) * Bsz];
    float* base1 = &d_Xg[((size_t)s * Gsz + cg1) * Bsz];
#pragma unroll
    for (int nt = 0; nt < 8; ++nt) {
        int n0 = nt * 8 + t * 2;
        *(float2*)&base0[n0] = make_float2(acc[nt][0] + bs0, acc[nt][1] + bs0);
        *(float2*)&base1[n0] = make_float2(acc[nt][2] + bs1, acc[nt][3] + bs1);
    }
}

// =================================================================================
// Phase B: 128 persistent blocks x 256 thr (mw=wid&3, nw=wid>>2).
// =================================================================================
__global__ void __launch_bounds__(256, 1) phaseB_kernel(
    const float* __restrict__ WaFw, const float* __restrict__ WaFb,
    const float* __restrict__ WaRw, const float* __restrict__ WaRb,
    const float* __restrict__ Fw,   const float* __restrict__ Fb,
    const float* __restrict__ Rw,   const float* __restrict__ Rb,
    float* __restrict__ out)
{
    const int tid = threadIdx.x, blk = blockIdx.x;
    const int cell = blk >> 6, u0 = (blk & 63) << 4;
    const int wid = tid >> 5, lane = tid & 31;
    const int mw = wid & 3, nw = wid >> 2;
    const int g = lane >> 2, t = lane & 3;

    __shared__ float gsm[64][68];
    __shared__ __align__(16) float hsh[2 * Hsz];
    __shared__ float lg[256];
    __shared__ float itm[64];
    __shared__ unsigned s_gen;

    {
        unsigned gi = blk * 256u + tid;
        if (gi < 32768) { __stcg(&d_Tp_hi[gi], 0u); __stcg(&d_Tp_lo[gi], 0u); }
    }
    if (tid == 0) s_gen = atomicAdd(&g_gen, 0u);
    __syncthreads();
    unsigned gen = s_gen;
    gridbar(gen);

    const uint4* pAh0 = (const uint4*)d_Wp_hi + (size_t)blk * 8192 + mw * 32 + lane;
    const uint4* pAl0 = (const uint4*)d_Wp_lo + (size_t)blk * 8192 + mw * 32 + lane;
    const uint4* pBh0 = (const uint4*)d_Tp_hi + nw * 4096 + lane * 2;
    const uint4* pBl0 = (const uint4*)d_Tp_lo + nw * 4096 + lane * 2;

    const int gu = tid >> 4, gb = (tid & 15) << 2;
    float cst[4] = {0.f, 0.f, 0.f, 0.f};

    float* outAF = out + (size_t)Bsz * Ssz * Hsz;
    float* outAR = outAF + (size_t)Bsz * Ssz * NS;

    for (int s = 0; s < Ssz; ++s) {
        // ---------------- recurrent GEMM (bf16x3 HMMA) --------------------------
        float acc[4][4];
#pragma unroll
        for (int n = 0; n < 4; ++n)
#pragma unroll
            for (int i = 0; i < 4; ++i) acc[n][i] = 0.f;

        const uint4* pAh = pAh0; const uint4* pAl = pAl0;
        const uint4* pBh = pBh0; const uint4* pBl = pBl0;
        uint4 cAh = __ldg(pAh), cAl = __ldg(pAl);
        uint4 cB0 = pBh[0], cB1 = pBh[1];
        uint4 cB2 = pBl[0], cB3 = pBl[1];

#pragma unroll 4
        for (int ks = 0; ks < 64; ++ks) {
            uint4 nAh, nAl, nB0, nB1, nB2, nB3;
            if (ks < 63) {
                pAh += 128; pAl += 128; pBh += 64; pBl += 64;
                nAh = __ldg(pAh); nAl = __ldg(pAl);
                nB0 = pBh[0]; nB1 = pBh[1];
                nB2 = pBl[0]; nB3 = pBl[1];
            }
            MMA16816(acc[0], cAh.x, cAh.y, cAh.z, cAh.w, cB0.x, cB0.y);
            MMA16816(acc[1], cAh.x, cAh.y, cAh.z, cAh.w, cB0.z, cB0.w);
            MMA16816(acc[2], cAh.x, cAh.y, cAh.z, cAh.w, cB1.x, cB1.y);
            MMA16816(acc[3], cAh.x, cAh.y, cAh.z, cAh.w, cB1.z, cB1.w);
            MMA16816(acc[0], cAh.x, cAh.y, cAh.z, cAh.w, cB2.x, cB2.y);
            MMA16816(acc[1], cAh.x, cAh.y, cAh.z, cAh.w, cB2.z, cB2.w);
            MMA16816(acc[2], cAh.x, cAh.y, cAh.z, cAh.w, cB3.x, cB3.y);
            MMA16816(acc[3], cAh.x, cAh.y, cAh.z, cAh.w, cB3.z, cB3.w);
            MMA16816(acc[0], cAl.x, cAl.y, cAl.z, cAl.w, cB0.x, cB0.y);
            MMA16816(acc[1], cAl.x, cAl.y, cAl.z, cAl.w, cB0.z, cB0.w);
            MMA16816(acc[2], cAl.x, cAl.y, cAl.z, cAl.w, cB1.x, cB1.y);
            MMA16816(acc[3], cAl.x, cAl.y, cAl.z, cAl.w, cB1.z, cB1.w);
            cAh = nAh; cAl = nAl; cB0 = nB0; cB1 = nB1; cB2 = nB2; cB3 = nB3;
        }

#pragma unroll
        for (int nt = 0; nt < 4; ++nt) {
            int col = nw * 32 + nt * 8 + t * 2;
            float* r0 = &gsm[mw * 16 + g][col];
            r0[0] = acc[nt][0]; r0[1] = acc[nt][1];
            float* r1 = &gsm[mw * 16 + g + 8][col];
            r1[0] = acc[nt][2]; r1[1] = acc[nt][3];
        }
        __syncthreads();

        // ---------------- gates ------------------------------------------------
        {
            float4 xg[4];
#pragma unroll
            for (int gate = 0; gate < 4; ++gate) {
                size_t col = (size_t)cell * H4 + (size_t)gate * Hsz + u0 + gu;
                xg[gate] = *reinterpret_cast<const float4*>(
                    &d_Xg[((size_t)s * Gsz + col) * Bsz + gb]);
            }
#pragma unroll
            for (int i = 0; i < 4; ++i) {
                int b = gb + i;
                float iv = gsm[      gu][b] + reinterpret_cast<const float*>(&xg[0])[i];
                float fv = gsm[16 + gu][b] + reinterpret_cast<const float*>(&xg[1])[i];
                float gv = gsm[32 + gu][b] + reinterpret_cast<const float*>(&xg[2])[i];
                float ov = gsm[48 + gu][b] + reinterpret_cast<const float*>(&xg[3])[i];
                float si = 1.f / (1.f + __expf(-iv));
                float sf = 1.f / (1.f + __expf(-fv));
                float so = 1.f / (1.f + __expf(-ov));
                float c2 = sf * cst[i] + si * tanhf(gv);
                cst[i] = c2;
                __stcg(&d_Hbuf[((size_t)cell * Bsz + b) * Hsz + u0 + gu], so * tanhf(c2));
            }
        }

        gridbar(gen);   // h complete

        // ---------------- attention: block b (<64) handles batch b -------------
        if (blk < Bsz) {
            const int b = blk;
            // stage hF|hR for this batch into smem (float4)
            {
                float4* hv = (float4*)hsh;
                const float4* src0 = (const float4*)&d_Hbuf[((size_t)0 * Bsz + b) * Hsz];
                const float4* src1 = (const float4*)&d_Hbuf[((size_t)1 * Bsz + b) * Hsz];
                for (int i = tid; i < 256; i += 256) {
                    hv[i]       = src0[i];
                    hv[256 + i] = src1[i];
                }
            }
            __syncthreads();

            // logits: 4 rows per warp concurrently, float4 loads (MLP >= 8)
            const float4* h4F = (const float4*)hsh;
            const float4* h4R = (const float4*)(hsh + Hsz);
            for (int r0 = wid * 4; r0 < NS + NR; r0 += 32) {
                const float4* wp[4]; const float4* hp[4]; float bs[4];
#pragma unroll
                for (int j = 0; j < 4; ++j) {
                    int r = r0 + j;
                    if (r < NS) {
                        wp[j] = (const float4*)(WaFw + (size_t)r * Hsz);
                        hp[j] = h4F; bs[j] = WaFb[r];
                    } else {
                        wp[j] = (const float4*)(WaRw + (size_t)(r - NS) * Hsz);
                        hp[j] = h4R; bs[j] = WaRb[r - NS];
                    }
                }
                float sr[4] = {0.f, 0.f, 0.f, 0.f};
#pragma unroll 2
                for (int i = lane; i < 256; i += 32) {
                    float4 w0 = __ldg(wp[0] + i);
                    float4 w1 = __ldg(wp[1] + i);
                    float4 w2 = __ldg(wp[2] + i);
                    float4 w3 = __ldg(wp[3] + i);
                    float4 h0 = hp[0][i], h1 = hp[1][i], h2 = hp[2][i], h3 = hp[3][i];
                    sr[0] = fmaf(w0.x, h0.x, fmaf(w0.y, h0.y, fmaf(w0.z, h0.z, fmaf(w0.w, h0.w, sr[0]))));
                    sr[1] = fmaf(w1.x, h1.x, fmaf(w1.y, h1.y, fmaf(w1.z, h1.z, fmaf(w1.w, h1.w, sr[1]))));
                    sr[2] = fmaf(w2.x, h2.x, fmaf(w2.y, h2.y, fmaf(w2.z, h2.z, fmaf(w2.w, h2.w, sr[2]))));
                    sr[3] = fmaf(w3.x, h3.x, fmaf(w3.y, h3.y, fmaf(w3.z, h3.z, fmaf(w3.w, h3.w, sr[3]))));
                }
#pragma unroll
                for (int j = 0; j < 4; ++j) {
                    float v = sr[j];
#pragma unroll
                    for (int off = 16; off; off >>= 1) v += __shfl_xor_sync(0xffffffffu, v, off);
                    if (lane == 0) lg[r0 + j] = v + bs[j];
                }
            }
            __syncthreads();

            if (wid == 0) {
                float m = -1e30f;
                for (int n = lane; n < NS; n += 32) m = fmaxf(m, lg[n]);
#pragma unroll
                for (int off = 16; off; off >>= 1) m = fmaxf(m, __shfl_xor_sync(0xffffffffu, m, off));
                float ssum = 0.f;
                for (int n = lane; n < NS; n += 32) { float e = __expf(lg[n] - m); lg[n] = e; ssum += e; }
#pragma unroll
                for (int off = 16; off; off >>= 1) ssum += __shfl_xor_sync(0xffffffffu, ssum, off);
                float inv = 1.f / ssum;
                for (int n = lane; n < NS; n += 32) {
                    float a = lg[n] * inv; lg[n] = a;
                    outAF[((size_t)b * Ssz + s) * NS + n] = a;
                }
            } else if (wid == 1) {
                float m = -1e30f;
                for (int n = lane; n < NR; n += 32) m = fmaxf(m, lg[NS + n]);
#pragma unroll
                for (int off = 16; off; off >>= 1) m = fmaxf(m, __shfl_xor_sync(0xffffffffu, m, off));
                float ssum = 0.f;
                for (int n = lane; n < NR; n += 32) { float e = __expf(lg[NS + n] - m); lg[NS + n] = e; ssum += e; }
#pragma unroll
                for (int off = 16; off; off >>= 1) ssum += __shfl_xor_sync(0xffffffffu, ssum, off);
                float inv = 1.f / ssum;
                for (int n = lane; n < NR; n += 32) {
                    float a = lg[NS + n] * inv; lg[NS + n] = a;
                    outAR[((size_t)b * Ssz + s) * NR + n] = a;
                }
            }
            __syncthreads();

            if (tid < 32) {
                float sum = Fb[tid];
                for (int n = 0; n < NS; ++n) sum = fmaf(lg[n], __ldg(&Fw[tid * NS + n]), sum);
                itm[tid] = sum;
            } else if (tid < 64) {
                int d = tid - 32;
                float sum = Rb[d];
                for (int n = 0; n < NR; ++n) sum = fmaf(lg[NS + n], __ldg(&Rw[d * NR + n]), sum);
                itm[32 + d] = sum;
            }
            __syncthreads();

            const int bnw = b >> 5, bnt = (b >> 3) & 3, bn = b & 7;
            for (int idx = tid; idx < 512; idx += 256) {
                int ks = idx >> 3, q = idx & 3, reg = (idx >> 2) & 1;
                int k0 = ks * 16 + reg * 8 + q * 2;
                float v0 = itm[k0 >> 5] * itm[32 + (k0 & 31)];
                float v1 = itm[(k0 + 1) >> 5] * itm[32 + ((k0 + 1) & 31)];
                out[((size_t)b * Ssz + s) * Hsz + k0]     = v0;
                out[((size_t)b * Ssz + s) * Hsz + k0 + 1] = v1;
                int fl = bn * 4 + q;
                int word = ((bnw * 64 + ks) * 32 + fl) * 8 + bnt * 2 + reg;
                __stcg(&d_Tp_hi[word], pack_hi(v0, v1));
                __stcg(&d_Tp_lo[word], pack_lo(v0, v1));
            }
        }

        gridbar(gen);   // T fragments complete for next step
    }
}

// =================================================================================
extern "C" void kernel_launch(void* const* d_in, const int* in_sizes, int n_in,
                              void* d_out, int out_size) {
    (void)in_sizes; (void)n_in; (void)out_size;
    const float* x    = (const float*)d_in[0];
    const float* WihF = (const float*)d_in[1];
    const float* WhhF = (const float*)d_in[2];
    const float* bihF = (const float*)d_in[3];
    const float* bhhF = (const float*)d_in[4];
    const float* WihR = (const float*)d_in[5];
    const float* WhhR = (const float*)d_in[6];
    const float* bihR = (const float*)d_in[7];
    const float* bhhR = (const float*)d_in[8];
    const float* WaFw = (const float*)d_in[9];
    const float* WaFb = (const float*)d_in[10];
    const float* WaRw = (const float*)d_in[11];
    const float* WaRb = (const float*)d_in[12];
    const float* Fw   = (const float*)d_in[13];
    const float* Fb   = (const float*)d_in[14];
    const float* Rw   = (const float*)d_in[15];
    const float* Rb   = (const float*)d_in[16];
    float* out = (float*)d_out;

    pack_whh_kernel<<<16384, 256>>>(WhhF, WhhR);
    pack_wih_kernel<<<25600, 256>>>(WihF, WihR);
    pack_x_kernel<<<12800, 256>>>(x);
    phaseA_mma_kernel<<<dim3(256, 64), 256>>>(bihF, bhhF, bihR, bhhR);
    phaseB_kernel<<<NBLK, 256>>>(WaFw, WaFb, WaRw, WaRb, Fw, Fb, Rw, Rb, out);
}